// round 10
// baseline (speedup 1.0000x reference)
#include <cuda_runtime.h>

#define BB 64
#define LL 2048
#define DD 128
#define HH 4
#define AA 128
#define MM 16
#define VV 100000
#define HDIM 32

// ---------------- scratch (one memset-able struct + derived tensors) ----------------
struct Acc {
    float  PhiPt[AA * MM];    // PhiP transposed [a][m]
    float  PhiQ[BB * AA];
    double sizeP[MM];
    double sumpS[BB * MM];
};
__device__ Acc  g_acc;
__device__ float g_pT[VV * MM];      // sigmoid(phi) transposed to [V][16]
__device__ float g_Y[MM * AA];       // Y[m][i] = sum_a W_A[a][i] * BP[m][a]
__device__ float g_Vp[MM * HDIM];    // PhiP @ W_val^T (no bias)

__device__ __forceinline__ int detect64(const void* ids) {
    const int* w = (const int*)ids;
    return (w[1] == 0 && w[3] == 0 && w[5] == 0 && w[7] == 0) ? 1 : 0;
}
__device__ __forceinline__ long long load_ll(const void* p, long long i, int is64) {
    return is64 ? ((const long long*)p)[i] : (long long)((const int*)p)[i];
}
__device__ __forceinline__ void red_add_v4(float* p, float4 v) {
    asm volatile("red.global.add.v4.f32 [%0], {%1,%2,%3,%4};"
                 :: "l"(p), "f"(v.x), "f"(v.y), "f"(v.z), "f"(v.w) : "memory");
}

// ---------------- K1: pT = sigmoid(phi)^T, PhiPt += p @ emb, sizeP ----------------
__global__ __launch_bounds__(256) void k_proto(const float* __restrict__ phi,
                                               const float* __restrict__ emb) {
    __shared__ float p_sh[256 * 20];              // [v][m], 80B row stride
    const int tid  = threadIdx.x;
    const int lane = tid & 31;
    const int wrp  = tid >> 5;
    const int v0   = blockIdx.x << 8;
    const int nv   = (VV - v0 < 256) ? (VV - v0) : 256;

    #pragma unroll
    for (int m = 0; m < 16; m++) {
        float p = 0.f;
        if (tid < nv) {
            float x = phi[m * VV + v0 + tid];
            p = 1.f / (1.f + expf(-x));
        }
        p_sh[tid * 20 + m] = p;
    }
    __syncthreads();
    {
        const int m0 = wrp * 2;
        float s0 = 0.f, s1 = 0.f;
        for (int v = lane; v < 256; v += 32) {
            s0 += p_sh[v * 20 + m0];
            s1 += p_sh[v * 20 + m0 + 1];
        }
        #pragma unroll
        for (int off = 16; off; off >>= 1) {
            s0 += __shfl_xor_sync(0xffffffffu, s0, off);
            s1 += __shfl_xor_sync(0xffffffffu, s1, off);
        }
        if (lane == 0) {
            atomicAdd(&g_acc.sizeP[m0],     (double)s0);
            atomicAdd(&g_acc.sizeP[m0 + 1], (double)s1);
        }
    }
    for (int j = tid; j < nv * 16; j += 256)
        g_pT[v0 * 16 + j] = p_sh[(j >> 4) * 20 + (j & 15)];

    // Phase B: FFMA2 rank-update (validated mapping, round 6/9)
    const int a = tid & 127;
    const int g = tid >> 7;
    unsigned long long acc[8];
    #pragma unroll
    for (int i = 0; i < 8; i++) acc[i] = 0ull;

    const unsigned pbase = (unsigned)__cvta_generic_to_shared(p_sh);
    const float* ep = emb + (long long)v0 * 128 + a + g * 128;
    const int iters = nv >> 3;
    unsigned saddr = pbase + (unsigned)g * 80;
    for (int it = 0; it < iters; it++) {
        float e0 = __ldg(ep);
        float e1 = __ldg(ep + 256);
        float e2 = __ldg(ep + 512);
        float e3 = __ldg(ep + 768);
        ep += 1024;
        #pragma unroll
        for (int u = 0; u < 4; u++) {
            float e = (u == 0) ? e0 : (u == 1) ? e1 : (u == 2) ? e2 : e3;
            unsigned long long ee, p01, p23, p45, p67;
            asm("mov.b64 %0, {%1,%1};" : "=l"(ee) : "f"(e));
            unsigned ad = saddr + (unsigned)u * 160;
            asm volatile("ld.shared.v2.u64 {%0,%1}, [%2];"      : "=l"(p01), "=l"(p23) : "r"(ad));
            asm volatile("ld.shared.v2.u64 {%0,%1}, [%2+32];"   : "=l"(p45), "=l"(p67) : "r"(ad));
            asm("fma.rn.f32x2 %0, %1, %2, %0;" : "+l"(acc[0]) : "l"(p01), "l"(ee));
            asm("fma.rn.f32x2 %0, %1, %2, %0;" : "+l"(acc[1]) : "l"(p23), "l"(ee));
            asm("fma.rn.f32x2 %0, %1, %2, %0;" : "+l"(acc[2]) : "l"(p45), "l"(ee));
            asm("fma.rn.f32x2 %0, %1, %2, %0;" : "+l"(acc[3]) : "l"(p67), "l"(ee));
            asm volatile("ld.shared.v2.u64 {%0,%1}, [%2+16];"   : "=l"(p01), "=l"(p23) : "r"(ad));
            asm volatile("ld.shared.v2.u64 {%0,%1}, [%2+48];"   : "=l"(p45), "=l"(p67) : "r"(ad));
            asm("fma.rn.f32x2 %0, %1, %2, %0;" : "+l"(acc[4]) : "l"(p01), "l"(ee));
            asm("fma.rn.f32x2 %0, %1, %2, %0;" : "+l"(acc[5]) : "l"(p23), "l"(ee));
            asm("fma.rn.f32x2 %0, %1, %2, %0;" : "+l"(acc[6]) : "l"(p45), "l"(ee));
            asm("fma.rn.f32x2 %0, %1, %2, %0;" : "+l"(acc[7]) : "l"(p67), "l"(ee));
        }
        saddr += 640;
    }
    float fa[16];
    {
        const int ord[8] = {0, 1, 4, 5, 2, 3, 6, 7};
        #pragma unroll
        for (int i = 0; i < 8; i++) {
            float lo, hi;
            asm("mov.b64 {%0,%1}, %2;" : "=f"(lo), "=f"(hi) : "l"(acc[ord[i]]));
            fa[2 * i] = lo; fa[2 * i + 1] = hi;
        }
    }
    __syncthreads();
    float* red = p_sh;
    if (g == 1) {
        #pragma unroll
        for (int mi = 0; mi < 16; mi++) red[mi * 128 + a] = fa[mi];
    }
    __syncthreads();
    if (g == 0) {
        #pragma unroll
        for (int mi = 0; mi < 16; mi++) fa[mi] += red[mi * 128 + a];
        float* dst = &g_acc.PhiPt[a * 16];
        red_add_v4(dst + 0,  make_float4(fa[0],  fa[1],  fa[2],  fa[3]));
        red_add_v4(dst + 4,  make_float4(fa[4],  fa[5],  fa[6],  fa[7]));
        red_add_v4(dst + 8,  make_float4(fa[8],  fa[9],  fa[10], fa[11]));
        red_add_v4(dst + 12, make_float4(fa[12], fa[13], fa[14], fa[15]));
    }
}

// ---------------- K2: gather + one extra block deriving Y/Vp from PhiPt ----------------
__global__ __launch_bounds__(256) void k_gather(const void* __restrict__ ids,
                                                const void* __restrict__ offs,
                                                const float* __restrict__ emb,
                                                const float* __restrict__ W_A,
                                                const float* __restrict__ W_B,
                                                const float* __restrict__ W_val) {
    __shared__ float  sred[8 * 136];
    __shared__ double sdd[8 * 17];
    const int tid = threadIdx.x;

    if (blockIdx.x == BB * 64) {
        // ---- derived-tensor block: BP, Y, Vp from PhiPt (runs concurrent w/ gather) ----
        __shared__ float sP[2048];
        __shared__ float sBP[16 * 128];
        for (int i = tid; i < 2048; i += 256) sP[i] = g_acc.PhiPt[i];
        __syncthreads();
        if (tid < 128) {
            float bp[16];
            #pragma unroll
            for (int m = 0; m < 16; m++) bp[m] = 0.f;
            const float4* W4 = (const float4*)(W_B + tid * 128);
            const float4* P4 = (const float4*)sP;
            for (int k4 = 0; k4 < 32; k4++) {
                float4 wv = __ldg(&W4[k4]);
                #pragma unroll
                for (int kk = 0; kk < 4; kk++) {
                    float wk = (kk == 0) ? wv.x : (kk == 1) ? wv.y : (kk == 2) ? wv.z : wv.w;
                    int k = k4 * 4 + kk;
                    float4 pA = P4[k * 4 + 0], pB = P4[k * 4 + 1];
                    float4 pC = P4[k * 4 + 2], pD = P4[k * 4 + 3];
                    bp[0]  += pA.x * wk; bp[1]  += pA.y * wk; bp[2]  += pA.z * wk; bp[3]  += pA.w * wk;
                    bp[4]  += pB.x * wk; bp[5]  += pB.y * wk; bp[6]  += pB.z * wk; bp[7]  += pB.w * wk;
                    bp[8]  += pC.x * wk; bp[9]  += pC.y * wk; bp[10] += pC.z * wk; bp[11] += pC.w * wk;
                    bp[12] += pD.x * wk; bp[13] += pD.y * wk; bp[14] += pD.z * wk; bp[15] += pD.w * wk;
                }
            }
            #pragma unroll
            for (int m = 0; m < 16; m++) sBP[m * 128 + tid] = bp[m];
        } else {
            // Vp[m][hd] on threads 128-255 (reads sP only)
            const int t2 = tid - 128;
            const int m = t2 >> 3, q = t2 & 7;
            float va[4] = {0.f, 0.f, 0.f, 0.f};
            for (int k4 = 0; k4 < 32; k4++) {
                float pm0 = sP[(k4*4+0)*16 + m];
                float pm1 = sP[(k4*4+1)*16 + m];
                float pm2 = sP[(k4*4+2)*16 + m];
                float pm3 = sP[(k4*4+3)*16 + m];
                #pragma unroll
                for (int r = 0; r < 4; r++) {
                    float4 wv = __ldg(&((const float4*)(W_val + (q*4+r) * 128))[k4]);
                    va[r] += pm0*wv.x + pm1*wv.y + pm2*wv.z + pm3*wv.w;
                }
            }
            #pragma unroll
            for (int r = 0; r < 4; r++) g_Vp[m * 32 + q*4 + r] = va[r];
        }
        __syncthreads();
        // Y[m][i] = sum_a W_A[a][i] * BP[m][a]   (threads 0-127, i = tid)
        if (tid < 128) {
            float y[16];
            #pragma unroll
            for (int m = 0; m < 16; m++) y[m] = 0.f;
            for (int a2 = 0; a2 < 128; a2++) {
                float wa = __ldg(&W_A[a2 * 128 + tid]);
                #pragma unroll
                for (int m = 0; m < 16; m++) y[m] += sBP[m * 128 + a2] * wa;
            }
            #pragma unroll
            for (int m = 0; m < 16; m++) g_Y[m * 128 + tid] = y[m];
        }
        return;
    }

    const int is64 = detect64(ids);
    const int b = blockIdx.x >> 6;
    const int s = blockIdx.x & 63;
    const long long start = load_ll(offs, b,     is64);
    const long long end   = load_ll(offs, b + 1, is64);
    const long long len   = end - start;
    const long long chunk = (len + 63) >> 6;
    const long long cs = start + (long long)s * chunk;
    long long ce = cs + chunk; if (ce > end) ce = end;

    const int w = tid >> 5, lane = tid & 31;
    const float4* emb4 = (const float4*)emb;
    float4 aq = make_float4(0.f, 0.f, 0.f, 0.f);
    double as = 0.0;

    long long i = cs + w;
    for (; i + 8 < ce; i += 16) {
        int id0 = (int)load_ll(ids, i,     is64);
        int id1 = (int)load_ll(ids, i + 8, is64);
        float4 e0 = __ldg(&emb4[id0 * 32 + lane]);
        float4 e1 = __ldg(&emb4[id1 * 32 + lane]);
        float p0 = 0.f, p1 = 0.f;
        if (lane < 16) { p0 = __ldg(&g_pT[id0 * 16 + lane]); p1 = __ldg(&g_pT[id1 * 16 + lane]); }
        aq.x += e0.x + e1.x; aq.y += e0.y + e1.y;
        aq.z += e0.z + e1.z; aq.w += e0.w + e1.w;
        as += (double)p0 + (double)p1;
    }
    for (; i < ce; i += 8) {
        int id = (int)load_ll(ids, i, is64);
        float4 e = __ldg(&emb4[id * 32 + lane]);
        aq.x += e.x; aq.y += e.y; aq.z += e.z; aq.w += e.w;
        if (lane < 16) as += (double)__ldg(&g_pT[id * 16 + lane]);
    }
    ((float4*)(sred + w * 136))[lane] = aq;
    if (lane < 16) sdd[w * 17 + lane] = as;
    __syncthreads();
    if (tid < 128) {
        float t = 0.f;
        #pragma unroll
        for (int w2 = 0; w2 < 8; w2++) t += sred[w2 * 136 + tid];
        sred[tid] = t;
    }
    if (tid < 16) {
        double td = 0.0;
        #pragma unroll
        for (int w2 = 0; w2 < 8; w2++) td += sdd[w2 * 17 + tid];
        atomicAdd(&g_acc.sumpS[b * 16 + tid], td);
    }
    __syncthreads();
    if (tid < 32) {
        float4 v = ((float4*)sred)[tid];
        red_add_v4(&g_acc.PhiQ[b * 128 + tid * 4], v);
    }
}

// ---------------- K3: tokens with per-block attn prologue; 8 tokens/warp ----------------
__global__ __launch_bounds__(256) void k_tokens(const float* __restrict__ ts,
        const void* __restrict__ ids, const void* __restrict__ offs,
        const float* __restrict__ size_w, const float* __restrict__ b_val,
        const float* __restrict__ W_out,
        const float* __restrict__ W_gate, const float* __restrict__ b_gate,
        const float* __restrict__ b_out, float* __restrict__ out) {
    __shared__ float wg[512];
    __shared__ float bo[128];
    __shared__ float bg[4];
    __shared__ float sPhiQ[128];
    __shared__ float Zs[32];
    __shared__ float sC[512];

    const int tid = threadIdx.x;
    const int b  = blockIdx.x >> 5;
    const int sb = blockIdx.x & 31;

    wg[tid] = W_gate[tid];
    wg[tid + 256] = W_gate[tid + 256];
    if (tid < 128) bo[tid] = b_out[tid];
    if (tid < 4)   bg[tid] = b_gate[tid];
    if (tid < 128) sPhiQ[tid] = g_acc.PhiQ[b * 128 + tid];
    __syncthreads();

    // ---- prologue: scores -> softmax -> Z (warp 0) ----
    if (tid < 32) {
        const int lane = tid;
        const int is64 = detect64(ids);
        const float sizeQ = (float)(load_ll(offs, b + 1, is64) - load_ll(offs, b, is64));
        const float sw0 = size_w[0], sw1 = size_w[1];
        float s[16];
        #pragma unroll
        for (int m = 0; m < 16; m++) {
            float part = 0.f;
            #pragma unroll
            for (int i = lane; i < 128; i += 32) part += sPhiQ[i] * __ldg(&g_Y[m * 128 + i]);
            #pragma unroll
            for (int off = 16; off; off >>= 1) part += __shfl_xor_sync(0xffffffffu, part, off);
            double sizeP = g_acc.sizeP[m];
            double sump  = g_acc.sumpS[b * 16 + m];
            double delta = (double)sizeQ + sizeP - 2.0 * sump;
            s[m] = (float)(-0.3 * delta + (double)part
                           + (double)sw0 * (double)sizeQ + (double)sw1 * sizeP);
        }
        float mx = s[0];
        #pragma unroll
        for (int m = 1; m < 16; m++) mx = fmaxf(mx, s[m]);
        float sum = 0.f;
        #pragma unroll
        for (int m = 0; m < 16; m++) { s[m] = expf(s[m] - mx); sum += s[m]; }
        const float inv = 1.f / sum;
        const float bvv = b_val[lane];
        float z = 0.f;
        #pragma unroll
        for (int m = 0; m < 16; m++) z += s[m] * inv * (__ldg(&g_Vp[m * 32 + lane]) + bvv);
        Zs[lane] = z;
    }
    __syncthreads();
    // ---- C[h][j] = sum_d Zs[d] * W_out[j][h*32+d]  (threads 0-127, j = tid) ----
    if (tid < 128) {
        const float4* Wo4 = (const float4*)(W_out + tid * 128);
        const float4* Z4  = (const float4*)Zs;
        #pragma unroll
        for (int h = 0; h < 4; h++) {
            float acc = 0.f;
            #pragma unroll
            for (int d = 0; d < 8; d++) {
                float4 wv = __ldg(&Wo4[h * 8 + d]);
                float4 zv = Z4[d];
                acc += zv.x*wv.x + zv.y*wv.y + zv.z*wv.z + zv.w*wv.w;
            }
            sC[h * 128 + tid] = acc;
        }
    }
    __syncthreads();

    // ---- token loop ----
    const int w = tid >> 5, lane = tid & 31;
    const int tok0 = b * 2048 + sb * 64 + w * 8;
    const int hsel = lane & 3;

    const float4* wg4 = (const float4*)wg;
    const float4 wgr0 = wg4[0 * 32 + lane];
    const float4 wgr1 = wg4[1 * 32 + lane];
    const float4 wgr2 = wg4[2 * 32 + lane];
    const float4 wgr3 = wg4[3 * 32 + lane];
    const float4* sC4 = (const float4*)sC;
    const float4 cA = sC4[(hsel ^ 0) * 32 + lane];
    const float4 cB = sC4[(hsel ^ 1) * 32 + lane];
    const float4 cC = sC4[(hsel ^ 2) * 32 + lane];
    const float4 cD = sC4[(hsel ^ 3) * 32 + lane];
    const float4 bov = ((const float4*)bo)[lane];
    const float bg_lane = bg[hsel];

    const float4* ts4 = (const float4*)ts;
    float4* out4 = (float4*)out;

    #pragma unroll 2
    for (int t = 0; t < 8; t++) {
        const long long token = tok0 + t;
        const float4 x = __ldg(&ts4[token * 32 + lane]);
        float a0 = x.x*wgr0.x + x.y*wgr0.y + x.z*wgr0.z + x.w*wgr0.w;
        float a1 = x.x*wgr1.x + x.y*wgr1.y + x.z*wgr1.z + x.w*wgr1.w;
        float a2 = x.x*wgr2.x + x.y*wgr2.y + x.z*wgr2.z + x.w*wgr2.w;
        float a3 = x.x*wgr3.x + x.y*wgr3.y + x.z*wgr3.z + x.w*wgr3.w;
        // fold: after 2 steps lane holds head (lane&3) partial over its 4-lane group
        const bool o1 = lane & 1, o2 = lane & 2;
        float s01 = o1 ? a1 : a0, x01 = o1 ? a0 : a1;
        float s23 = o1 ? a3 : a2, x23 = o1 ? a2 : a3;
        s01 += __shfl_xor_sync(0xffffffffu, x01, 1);
        s23 += __shfl_xor_sync(0xffffffffu, x23, 1);
        float v = o2 ? s23 : s01, xv = o2 ? s01 : s23;
        v += __shfl_xor_sync(0xffffffffu, xv, 2);
        v += __shfl_xor_sync(0xffffffffu, v, 4);
        v += __shfl_xor_sync(0xffffffffu, v, 8);
        v += __shfl_xor_sync(0xffffffffu, v, 16);
        float gsc = v + bg_lane;
        // softmax over heads within 4-lane group
        float m1 = fmaxf(gsc, __shfl_xor_sync(0xffffffffu, gsc, 1));
        float mx = fmaxf(m1, __shfl_xor_sync(0xffffffffu, m1, 2));
        float e  = __expf(gsc - mx);
        float s1 = e + __shfl_xor_sync(0xffffffffu, e, 1);
        float ssum = s1 + __shfl_xor_sync(0xffffffffu, s1, 2);
        float ge = e * __frcp_rn(ssum);
        float p1 = __shfl_xor_sync(0xffffffffu, ge, 1);
        float p2 = __shfl_xor_sync(0xffffffffu, ge, 2);
        float p3 = __shfl_xor_sync(0xffffffffu, ge, 3);

        float4 o = bov;
        o.x += ge*cA.x + p1*cB.x + p2*cC.x + p3*cD.x;
        o.y += ge*cA.y + p1*cB.y + p2*cC.y + p3*cD.y;
        o.z += ge*cA.z + p1*cB.z + p2*cC.z + p3*cD.z;
        o.w += ge*cA.w + p1*cB.w + p2*cC.w + p3*cD.w;
        out4[token * 32 + lane] = o;
    }
}

// ---------------- launch (serial stream order) ----------------
extern "C" void kernel_launch(void* const* d_in, const int* in_sizes, int n_in,
                              void* d_out, int out_size) {
    const float* ts    = (const float*)d_in[0];
    const void*  ids   = d_in[1];
    const void*  offs  = d_in[2];
    const float* emb   = (const float*)d_in[3];
    const float* phi   = (const float*)d_in[4];
    const float* W_A   = (const float*)d_in[5];
    const float* W_B   = (const float*)d_in[6];
    const float* W_val = (const float*)d_in[7];
    const float* b_val = (const float*)d_in[8];
    const float* W_g   = (const float*)d_in[9];
    const float* b_g   = (const float*)d_in[10];
    const float* W_o   = (const float*)d_in[11];
    const float* b_o   = (const float*)d_in[12];
    const float* szw   = (const float*)d_in[13];

    void* accp = nullptr;
    cudaGetSymbolAddress(&accp, g_acc);
    cudaMemsetAsync(accp, 0, sizeof(Acc), 0);

    k_proto <<<(VV + 255) / 256, 256>>>(phi, emb);
    k_gather<<<BB * 64 + 1, 256>>>(ids, offs, emb, W_A, W_B, W_val);
    k_tokens<<<BB * 32, 256>>>(ts, ids, offs, szw, b_val, W_o, W_g, b_g, b_o, (float*)d_out);
}

// round 14
// speedup vs baseline: 1.2319x; 1.2319x over previous
#include <cuda_runtime.h>

#define BB 64
#define LL 2048
#define DD 128
#define HH 4
#define AA 128
#define MM 16
#define VV 100000
#define HDIM 32

// ---------------- scratch ----------------
struct Acc {
    float  PhiPt[AA * MM];    // PhiP transposed [a][m]
    float  PhiQ[BB * AA];
    double sizeP[MM];
    double sumpS[BB * MM];
};
__device__ Acc  g_acc;
__device__ float g_pT[VV * MM];      // sigmoid(phi) transposed to [V][16]
__device__ float g_Y[MM * AA];       // Y[m][i] = sum_a W_A[a][i] * BP[m][a]
__device__ float g_Vp[MM * HDIM];    // PhiP @ W_val^T (no bias)
__device__ float g_C[BB * HH * DD];

__device__ __forceinline__ int detect64(const void* ids) {
    const int* w = (const int*)ids;
    return (w[1] == 0 && w[3] == 0 && w[5] == 0 && w[7] == 0) ? 1 : 0;
}
__device__ __forceinline__ long long load_ll(const void* p, long long i, int is64) {
    return is64 ? ((const long long*)p)[i] : (long long)((const int*)p)[i];
}
__device__ __forceinline__ void red_add_v4(float* p, float4 v) {
    asm volatile("red.global.add.v4.f32 [%0], {%1,%2,%3,%4};"
                 :: "l"(p), "f"(v.x), "f"(v.y), "f"(v.z), "f"(v.w) : "memory");
}

// ---------------- K1: 128-vocab slabs, 782 blocks ----------------
__global__ __launch_bounds__(256) void k_proto(const float* __restrict__ phi,
                                               const float* __restrict__ emb) {
    __shared__ float p_sh[128 * 20];              // [v][m], 80B row stride (10KB)
    const int tid  = threadIdx.x;
    const int lane = tid & 31;
    const int wrp  = tid >> 5;
    const int v0   = blockIdx.x << 7;
    const int nv   = (VV - v0 < 128) ? (VV - v0) : 128;

    // Phase A: sigmoid -> shared (zeros beyond nv)
    #pragma unroll
    for (int j = tid; j < 2048; j += 256) {
        const int m = j >> 7, vi = j & 127;
        float p = 0.f;
        if (vi < nv) {
            float x = phi[m * VV + v0 + vi];
            p = 1.f / (1.f + expf(-x));
        }
        p_sh[vi * 20 + m] = p;
    }
    __syncthreads();
    // sizeP: warp wrp reduces prototypes 2*wrp, 2*wrp+1
    {
        const int m0 = wrp * 2;
        float s0 = 0.f, s1 = 0.f;
        #pragma unroll
        for (int v = lane; v < 128; v += 32) {
            s0 += p_sh[v * 20 + m0];
            s1 += p_sh[v * 20 + m0 + 1];
        }
        #pragma unroll
        for (int off = 16; off; off >>= 1) {
            s0 += __shfl_xor_sync(0xffffffffu, s0, off);
            s1 += __shfl_xor_sync(0xffffffffu, s1, off);
        }
        if (lane == 0) {
            atomicAdd(&g_acc.sizeP[m0],     (double)s0);
            atomicAdd(&g_acc.sizeP[m0 + 1], (double)s1);
        }
    }
    // pT write (coalesced)
    for (int j = tid; j < nv * 16; j += 256)
        g_pT[v0 * 16 + j] = p_sh[(j >> 4) * 20 + (j & 15)];

    // Phase B: FFMA2 rank-update (validated inner loop + mapping)
    const int a = tid & 127;
    const int g = tid >> 7;
    unsigned long long acc[8];
    #pragma unroll
    for (int i = 0; i < 8; i++) acc[i] = 0ull;

    const unsigned pbase = (unsigned)__cvta_generic_to_shared(p_sh);
    const float* ep = emb + (long long)v0 * 128 + a + g * 128;
    const int iters = nv >> 3;                    // nv divisible by 8 (128 or 32)
    unsigned saddr = pbase + (unsigned)g * 80;
    for (int it = 0; it < iters; it++) {
        float e0 = __ldg(ep);
        float e1 = __ldg(ep + 256);
        float e2 = __ldg(ep + 512);
        float e3 = __ldg(ep + 768);
        ep += 1024;
        #pragma unroll
        for (int u = 0; u < 4; u++) {
            float e = (u == 0) ? e0 : (u == 1) ? e1 : (u == 2) ? e2 : e3;
            unsigned long long ee, p01, p23, p45, p67;
            asm("mov.b64 %0, {%1,%1};" : "=l"(ee) : "f"(e));
            unsigned ad = saddr + (unsigned)u * 160;
            asm volatile("ld.shared.v2.u64 {%0,%1}, [%2];"      : "=l"(p01), "=l"(p23) : "r"(ad));
            asm volatile("ld.shared.v2.u64 {%0,%1}, [%2+32];"   : "=l"(p45), "=l"(p67) : "r"(ad));
            asm("fma.rn.f32x2 %0, %1, %2, %0;" : "+l"(acc[0]) : "l"(p01), "l"(ee));
            asm("fma.rn.f32x2 %0, %1, %2, %0;" : "+l"(acc[1]) : "l"(p23), "l"(ee));
            asm("fma.rn.f32x2 %0, %1, %2, %0;" : "+l"(acc[2]) : "l"(p45), "l"(ee));
            asm("fma.rn.f32x2 %0, %1, %2, %0;" : "+l"(acc[3]) : "l"(p67), "l"(ee));
            asm volatile("ld.shared.v2.u64 {%0,%1}, [%2+16];"   : "=l"(p01), "=l"(p23) : "r"(ad));
            asm volatile("ld.shared.v2.u64 {%0,%1}, [%2+48];"   : "=l"(p45), "=l"(p67) : "r"(ad));
            asm("fma.rn.f32x2 %0, %1, %2, %0;" : "+l"(acc[4]) : "l"(p01), "l"(ee));
            asm("fma.rn.f32x2 %0, %1, %2, %0;" : "+l"(acc[5]) : "l"(p23), "l"(ee));
            asm("fma.rn.f32x2 %0, %1, %2, %0;" : "+l"(acc[6]) : "l"(p45), "l"(ee));
            asm("fma.rn.f32x2 %0, %1, %2, %0;" : "+l"(acc[7]) : "l"(p67), "l"(ee));
        }
        saddr += 640;
    }
    float fa[16];
    {
        const int ord[8] = {0, 1, 4, 5, 2, 3, 6, 7};
        #pragma unroll
        for (int i = 0; i < 8; i++) {
            float lo, hi;
            asm("mov.b64 {%0,%1}, %2;" : "=f"(lo), "=f"(hi) : "l"(acc[ord[i]]));
            fa[2 * i] = lo; fa[2 * i + 1] = hi;
        }
    }
    __syncthreads();
    float* red = p_sh;                            // reuse as [m][a] (8KB <= 10KB)
    if (g == 1) {
        #pragma unroll
        for (int mi = 0; mi < 16; mi++) red[mi * 128 + a] = fa[mi];
    }
    __syncthreads();
    if (g == 0) {
        #pragma unroll
        for (int mi = 0; mi < 16; mi++) fa[mi] += red[mi * 128 + a];
        float* dst = &g_acc.PhiPt[a * 16];
        red_add_v4(dst + 0,  make_float4(fa[0],  fa[1],  fa[2],  fa[3]));
        red_add_v4(dst + 4,  make_float4(fa[4],  fa[5],  fa[6],  fa[7]));
        red_add_v4(dst + 8,  make_float4(fa[8],  fa[9],  fa[10], fa[11]));
        red_add_v4(dst + 12, make_float4(fa[12], fa[13], fa[14], fa[15]));
    }
}

// ---------------- K2: gather + one extra block deriving Y/Vp from PhiPt ----------------
__global__ __launch_bounds__(256) void k_gather(const void* __restrict__ ids,
                                                const void* __restrict__ offs,
                                                const float* __restrict__ emb,
                                                const float* __restrict__ W_A,
                                                const float* __restrict__ W_B,
                                                const float* __restrict__ W_val) {
    __shared__ float  sred[8 * 136];
    __shared__ double sdd[8 * 17];
    const int tid = threadIdx.x;

    if (blockIdx.x == BB * 64) {
        // ---- derived-tensor block (validated round 10) ----
        __shared__ float sP[2048];
        __shared__ float sBP[16 * 128];
        for (int i = tid; i < 2048; i += 256) sP[i] = g_acc.PhiPt[i];
        __syncthreads();
        if (tid < 128) {
            float bp[16];
            #pragma unroll
            for (int m = 0; m < 16; m++) bp[m] = 0.f;
            const float4* W4 = (const float4*)(W_B + tid * 128);
            const float4* P4 = (const float4*)sP;
            for (int k4 = 0; k4 < 32; k4++) {
                float4 wv = __ldg(&W4[k4]);
                #pragma unroll
                for (int kk = 0; kk < 4; kk++) {
                    float wk = (kk == 0) ? wv.x : (kk == 1) ? wv.y : (kk == 2) ? wv.z : wv.w;
                    int k = k4 * 4 + kk;
                    float4 pA = P4[k * 4 + 0], pB = P4[k * 4 + 1];
                    float4 pC = P4[k * 4 + 2], pD = P4[k * 4 + 3];
                    bp[0]  += pA.x * wk; bp[1]  += pA.y * wk; bp[2]  += pA.z * wk; bp[3]  += pA.w * wk;
                    bp[4]  += pB.x * wk; bp[5]  += pB.y * wk; bp[6]  += pB.z * wk; bp[7]  += pB.w * wk;
                    bp[8]  += pC.x * wk; bp[9]  += pC.y * wk; bp[10] += pC.z * wk; bp[11] += pC.w * wk;
                    bp[12] += pD.x * wk; bp[13] += pD.y * wk; bp[14] += pD.z * wk; bp[15] += pD.w * wk;
                }
            }
            #pragma unroll
            for (int m = 0; m < 16; m++) sBP[m * 128 + tid] = bp[m];
        } else {
            const int t2 = tid - 128;
            const int m = t2 >> 3, q = t2 & 7;
            float va[4] = {0.f, 0.f, 0.f, 0.f};
            for (int k4 = 0; k4 < 32; k4++) {
                float pm0 = sP[(k4*4+0)*16 + m];
                float pm1 = sP[(k4*4+1)*16 + m];
                float pm2 = sP[(k4*4+2)*16 + m];
                float pm3 = sP[(k4*4+3)*16 + m];
                #pragma unroll
                for (int r = 0; r < 4; r++) {
                    float4 wv = __ldg(&((const float4*)(W_val + (q*4+r) * 128))[k4]);
                    va[r] += pm0*wv.x + pm1*wv.y + pm2*wv.z + pm3*wv.w;
                }
            }
            #pragma unroll
            for (int r = 0; r < 4; r++) g_Vp[m * 32 + q*4 + r] = va[r];
        }
        __syncthreads();
        if (tid < 128) {
            float y[16];
            #pragma unroll
            for (int m = 0; m < 16; m++) y[m] = 0.f;
            for (int a2 = 0; a2 < 128; a2++) {
                float wa = __ldg(&W_A[a2 * 128 + tid]);
                #pragma unroll
                for (int m = 0; m < 16; m++) y[m] += sBP[m * 128 + a2] * wa;
            }
            #pragma unroll
            for (int m = 0; m < 16; m++) g_Y[m * 128 + tid] = y[m];
        }
        return;
    }

    const int is64 = detect64(ids);
    const int b = blockIdx.x >> 6;
    const int s = blockIdx.x & 63;
    const long long start = load_ll(offs, b,     is64);
    const long long end   = load_ll(offs, b + 1, is64);
    const long long len   = end - start;
    const long long chunk = (len + 63) >> 6;
    const long long cs = start + (long long)s * chunk;
    long long ce = cs + chunk; if (ce > end) ce = end;

    const int w = tid >> 5, lane = tid & 31;
    const float4* emb4 = (const float4*)emb;
    float4 aq = make_float4(0.f, 0.f, 0.f, 0.f);
    double as = 0.0;

    long long i = cs + w;
    for (; i + 8 < ce; i += 16) {
        int id0 = (int)load_ll(ids, i,     is64);
        int id1 = (int)load_ll(ids, i + 8, is64);
        float4 e0 = __ldg(&emb4[id0 * 32 + lane]);
        float4 e1 = __ldg(&emb4[id1 * 32 + lane]);
        float p0 = 0.f, p1 = 0.f;
        if (lane < 16) { p0 = __ldg(&g_pT[id0 * 16 + lane]); p1 = __ldg(&g_pT[id1 * 16 + lane]); }
        aq.x += e0.x + e1.x; aq.y += e0.y + e1.y;
        aq.z += e0.z + e1.z; aq.w += e0.w + e1.w;
        as += (double)p0 + (double)p1;
    }
    for (; i < ce; i += 8) {
        int id = (int)load_ll(ids, i, is64);
        float4 e = __ldg(&emb4[id * 32 + lane]);
        aq.x += e.x; aq.y += e.y; aq.z += e.z; aq.w += e.w;
        if (lane < 16) as += (double)__ldg(&g_pT[id * 16 + lane]);
    }
    ((float4*)(sred + w * 136))[lane] = aq;
    if (lane < 16) sdd[w * 17 + lane] = as;
    __syncthreads();
    if (tid < 128) {
        float t = 0.f;
        #pragma unroll
        for (int w2 = 0; w2 < 8; w2++) t += sred[w2 * 136 + tid];
        sred[tid] = t;
    }
    if (tid < 16) {
        double td = 0.0;
        #pragma unroll
        for (int w2 = 0; w2 < 8; w2++) td += sdd[w2 * 17 + tid];
        atomicAdd(&g_acc.sumpS[b * 16 + tid], td);
    }
    __syncthreads();
    if (tid < 32) {
        float4 v = ((float4*)sred)[tid];
        red_add_v4(&g_acc.PhiQ[b * 128 + tid * 4], v);
    }
}

// ---------------- K3: cheap attn: scores from PhiQ . Y, softmax, Z, C ----------------
__global__ __launch_bounds__(128) void k_attn(const void* __restrict__ ids,
        const void* __restrict__ offs, const float* __restrict__ size_w,
        const float* __restrict__ b_val, const float* __restrict__ W_out) {
    __shared__ float Zs[32];
    const int b = blockIdx.x;
    const int tid = threadIdx.x;

    if (tid < 32) {
        const int lane = tid;
        const float pq0 = g_acc.PhiQ[b * 128 + lane];
        const float pq1 = g_acc.PhiQ[b * 128 + lane + 32];
        const float pq2 = g_acc.PhiQ[b * 128 + lane + 64];
        const float pq3 = g_acc.PhiQ[b * 128 + lane + 96];
        const int is64 = detect64(ids);
        const float sizeQ = (float)(load_ll(offs, b + 1, is64) - load_ll(offs, b, is64));
        const float sw0 = size_w[0], sw1 = size_w[1];
        float s[16];
        #pragma unroll
        for (int m = 0; m < 16; m++) {
            const float* Ym = g_Y + m * 128;
            float part = pq0 * __ldg(&Ym[lane])      + pq1 * __ldg(&Ym[lane + 32])
                       + pq2 * __ldg(&Ym[lane + 64]) + pq3 * __ldg(&Ym[lane + 96]);
            #pragma unroll
            for (int off = 16; off; off >>= 1) part += __shfl_xor_sync(0xffffffffu, part, off);
            double sizeP = g_acc.sizeP[m];
            double sump  = g_acc.sumpS[b * 16 + m];
            double delta = (double)sizeQ + sizeP - 2.0 * sump;
            s[m] = (float)(-0.3 * delta + (double)part
                           + (double)sw0 * (double)sizeQ + (double)sw1 * sizeP);
        }
        float mx = s[0];
        #pragma unroll
        for (int m = 1; m < 16; m++) mx = fmaxf(mx, s[m]);
        float sum = 0.f;
        #pragma unroll
        for (int m = 0; m < 16; m++) { s[m] = expf(s[m] - mx); sum += s[m]; }
        const float inv = 1.f / sum;
        const float bvv = b_val[lane];
        float z = 0.f;
        #pragma unroll
        for (int m = 0; m < 16; m++) z += s[m] * inv * (__ldg(&g_Vp[m * 32 + lane]) + bvv);
        Zs[lane] = z;
    }
    __syncthreads();
    const int j = tid;
    const float4* Wo4 = (const float4*)(W_out + j * 128);
    const float4* Z4  = (const float4*)Zs;
    #pragma unroll
    for (int h = 0; h < 4; h++) {
        float acc = 0.f;
        #pragma unroll
        for (int d = 0; d < 8; d++) {
            float4 wv = __ldg(&Wo4[h * 8 + d]);
            float4 zv = Z4[d];
            acc += zv.x*wv.x + zv.y*wv.y + zv.z*wv.z + zv.w*wv.w;
        }
        g_C[b * 512 + h * 128 + j] = acc;
    }
}

// ---------------- K4: tokens; 8 tokens/warp; fold-transpose softmax (validated) ----------------
__global__ __launch_bounds__(256) void k_tokens(const float* __restrict__ ts,
        const float* __restrict__ W_gate, const float* __restrict__ b_gate,
        const float* __restrict__ b_out, float* __restrict__ out) {
    __shared__ float wg[512];
    __shared__ float bo[128];
    __shared__ float bg[4];
    const int tid = threadIdx.x;
    wg[tid] = W_gate[tid];
    wg[tid + 256] = W_gate[tid + 256];
    if (tid < 128) bo[tid] = b_out[tid];
    if (tid < 4)   bg[tid] = b_gate[tid];
    __syncthreads();

    const int w = tid >> 5, lane = tid & 31;
    const int tok0 = (blockIdx.x * 8 + w) * 8;       // 8 consecutive tokens, same b
    const int b = tok0 >> 11;                        // L = 2048
    const int hsel = lane & 3;

    const float4* wg4 = (const float4*)wg;
    const float4 wgr0 = wg4[0 * 32 + lane];
    const float4 wgr1 = wg4[1 * 32 + lane];
    const float4 wgr2 = wg4[2 * 32 + lane];
    const float4 wgr3 = wg4[3 * 32 + lane];
    const float4* C4 = (const float4*)(g_C + b * 512);
    const float4 cA = __ldg(&C4[(hsel ^ 0) * 32 + lane]);
    const float4 cB = __ldg(&C4[(hsel ^ 1) * 32 + lane]);
    const float4 cC = __ldg(&C4[(hsel ^ 2) * 32 + lane]);
    const float4 cD = __ldg(&C4[(hsel ^ 3) * 32 + lane]);
    const float4 bov = ((const float4*)bo)[lane];
    const float bg_lane = bg[hsel];

    const float4* ts4 = (const float4*)ts;
    float4* out4 = (float4*)out;

    #pragma unroll 2
    for (int t = 0; t < 8; t++) {
        const long long token = tok0 + t;
        const float4 x = __ldg(&ts4[token * 32 + lane]);
        float a0 = x.x*wgr0.x + x.y*wgr0.y + x.z*wgr0.z + x.w*wgr0.w;
        float a1 = x.x*wgr1.x + x.y*wgr1.y + x.z*wgr1.z + x.w*wgr1.w;
        float a2 = x.x*wgr2.x + x.y*wgr2.y + x.z*wgr2.z + x.w*wgr2.w;
        float a3 = x.x*wgr3.x + x.y*wgr3.y + x.z*wgr3.z + x.w*wgr3.w;
        const bool o1 = lane & 1, o2 = lane & 2;
        float s01 = o1 ? a1 : a0, x01 = o1 ? a0 : a1;
        float s23 = o1 ? a3 : a2, x23 = o1 ? a2 : a3;
        s01 += __shfl_xor_sync(0xffffffffu, x01, 1);
        s23 += __shfl_xor_sync(0xffffffffu, x23, 1);
        float v = o2 ? s23 : s01, xv = o2 ? s01 : s23;
        v += __shfl_xor_sync(0xffffffffu, xv, 2);
        v += __shfl_xor_sync(0xffffffffu, v, 4);
        v += __shfl_xor_sync(0xffffffffu, v, 8);
        v += __shfl_xor_sync(0xffffffffu, v, 16);
        float gsc = v + bg_lane;
        float m1 = fmaxf(gsc, __shfl_xor_sync(0xffffffffu, gsc, 1));
        float mx = fmaxf(m1, __shfl_xor_sync(0xffffffffu, m1, 2));
        float e  = __expf(gsc - mx);
        float s1 = e + __shfl_xor_sync(0xffffffffu, e, 1);
        float ssum = s1 + __shfl_xor_sync(0xffffffffu, s1, 2);
        float ge = e * __frcp_rn(ssum);
        float p1 = __shfl_xor_sync(0xffffffffu, ge, 1);
        float p2 = __shfl_xor_sync(0xffffffffu, ge, 2);
        float p3 = __shfl_xor_sync(0xffffffffu, ge, 3);

        float4 o = bov;
        o.x += ge*cA.x + p1*cB.x + p2*cC.x + p3*cD.x;
        o.y += ge*cA.y + p1*cB.y + p2*cC.y + p3*cD.y;
        o.z += ge*cA.z + p1*cB.z + p2*cC.z + p3*cD.z;
        o.w += ge*cA.w + p1*cB.w + p2*cC.w + p3*cD.w;
        out4[token * 32 + lane] = o;
    }
}

// ---------------- launch (serial stream order) ----------------
extern "C" void kernel_launch(void* const* d_in, const int* in_sizes, int n_in,
                              void* d_out, int out_size) {
    const float* ts    = (const float*)d_in[0];
    const void*  ids   = d_in[1];
    const void*  offs  = d_in[2];
    const float* emb   = (const float*)d_in[3];
    const float* phi   = (const float*)d_in[4];
    const float* W_A   = (const float*)d_in[5];
    const float* W_B   = (const float*)d_in[6];
    const float* W_val = (const float*)d_in[7];
    const float* b_val = (const float*)d_in[8];
    const float* W_g   = (const float*)d_in[9];
    const float* b_g   = (const float*)d_in[10];
    const float* W_o   = (const float*)d_in[11];
    const float* b_o   = (const float*)d_in[12];
    const float* szw   = (const float*)d_in[13];

    void* accp = nullptr;
    cudaGetSymbolAddress(&accp, g_acc);
    cudaMemsetAsync(accp, 0, sizeof(Acc), 0);

    k_proto <<<(VV + 127) / 128, 256>>>(phi, emb);
    k_gather<<<BB * 64 + 1, 256>>>(ids, offs, emb, W_A, W_B, W_val);
    k_attn  <<<BB, 128>>>(ids, offs, szw, b_val, W_o);
    k_tokens<<<(BB * LL) / 64, 256>>>(ts, W_g, b_g, b_o, (float*)d_out);
}